// round 12
// baseline (speedup 1.0000x reference)
#include <cuda_runtime.h>
#include <cstdint>

#define SEQ   2048
#define HID   512
#define TAPS  64
#define SC    64       // seq rows per CTA
#define UGRP  8        // rows per inner group
#define HTAPS 32       // taps per thread-half
#define WSPAN (HTAPS + UGRP - 1)   // 39 live window rows per half
#define HBUF_PAIRS 256 // 512 channels as u64 pairs per row

typedef unsigned long long u64;

__device__ __forceinline__ u64 fma2(u64 a, u64 b, u64 c) {
    u64 d;
    asm("fma.rn.f32x2 %0, %1, %2, %3;" : "=l"(d) : "l"(a), "l"(b), "l"(c));
    return d;
}
__device__ __forceinline__ u64 add2(u64 a, u64 b) {
    u64 d;
    asm("add.rn.f32x2 %0, %1, %2;" : "=l"(d) : "l"(a), "l"(b));
    return d;
}
__device__ __forceinline__ float lo32(u64 v) { return __uint_as_float((unsigned)v); }
__device__ __forceinline__ float hi32(u64 v) { return __uint_as_float((unsigned)(v >> 32)); }
__device__ __forceinline__ u64 pack2(float l, float h) {
    return ((u64)__float_as_uint(h) << 32) | (u64)__float_as_uint(l);
}

// Pairwise named barrier: syncs exactly 2 warps (64 threads) — warp w (h=0)
// with warp w+4 (h=1), which exchange partials for the same channel pairs.
__device__ __forceinline__ void bar_pair(int id) {
    asm volatile("bar.sync %0, 64;" :: "r"(id) : "memory");
}

// Fused: circular depthwise conv (64 taps, packed f32x2) + residual + LayerNorm.
// CTA = 64 seq rows x all 512 channels (two 256-channel passes).
// 256 threads = 128 channel-pairs x 2 tap-halves; weights + sliding window in
// registers. Tap-half combine synced per WARP-PAIR (named barrier, 64 thr) so
// the 4 pairs slip independently — no CTA-wide barrier in the conv loop.
extern __shared__ u64 dsm[];

__global__ __launch_bounds__(256, 1) void fconv_ln_kernel(
    const float* __restrict__ x,
    const float* __restrict__ w,
    const float* __restrict__ gamma,
    const float* __restrict__ beta,
    float* __restrict__ out)
{
    u64* hbuf = dsm;                          // [SC][HBUF_PAIRS] 128KB
    u64* part = dsm + SC * HBUF_PAIRS;        // [2][UGRP][128]   16KB

    const int tid = threadIdx.x;
    const int p   = tid & 127;          // channel pair within group
    const int h   = tid >> 7;           // tap half: 0 -> taps 0..31, 1 -> 32..63
    const int bar = 1 + ((tid >> 5) & 3);   // pair barrier id (warps w, w+4)
    const int b   = blockIdx.y;
    const int s0  = blockIdx.x * SC;

    const float ks = 0.022097086912079608f;   // 1/sqrt(2048)
    const u64 sc2 = pack2(ks, ks);

#pragma unroll 1
    for (int cg = 0; cg < 2; ++cg) {
        const int c = cg * 256 + p * 2;
        const u64* __restrict__ xb =
            reinterpret_cast<const u64*>(x + (size_t)b * (SEQ * HID) + c);
        const int slotc = cg * 128 + p;

        // This half's 32 tap-weights for this channel pair (registers).
        u64 wr[HTAPS];
#pragma unroll
        for (int k = 0; k < HTAPS; ++k)
            wr[k] = *reinterpret_cast<const u64*>(w + (k + HTAPS * h) * HID + c);

        // Window: win[i] = x[(s0 - 32h - 31 + i) mod SEQ], i in [0,39)
        u64 win[WSPAN];
#pragma unroll
        for (int i = 0; i < WSPAN; ++i) {
            int row = (s0 + SEQ - HTAPS * h - (HTAPS - 1) + i) & (SEQ - 1);
            win[i] = xb[row * (HID / 2)];
        }

#pragma unroll 1
        for (int g = 0; g < SC / UGRP; ++g) {
            const int sb  = s0 + g * UGRP;
            const int rl  = g * UGRP;
            const int buf = g & 1;

            // Prefetch next UGRP window rows (hidden under this group's FMAs).
            u64 nxt[UGRP];
#pragma unroll
            for (int i = 0; i < UGRP; ++i) {
                int row = (sb + SEQ - HTAPS * h + UGRP + i) & (SEQ - 1);
                nxt[i] = xb[row * (HID / 2)];
            }

            // 32-tap partials: acc[j] = sum_t wr[t] * win[31+j-t]
            u64 acc[UGRP];
#pragma unroll
            for (int j = 0; j < UGRP; ++j) acc[j] = 0ull;
#pragma unroll 4
            for (int t = 0; t < HTAPS; ++t) {
#pragma unroll
                for (int j = 0; j < UGRP; ++j)
                    acc[j] = fma2(wr[t], win[HTAPS - 1 + j - t], acc[j]);
            }

            // Pairwise exchange: h=1 stores, pair-barrier, h=0 combines.
            // Double-buffered part: h0's read of buf (g-2) precedes its g-1
            // barrier, which precedes h1's write of buf (g) — race-free.
            if (h) {
                u64* pp = part + (buf * UGRP) * 128 + p;
#pragma unroll
                for (int j = 0; j < UGRP; ++j) pp[j * 128] = acc[j];
            }
            bar_pair(bar);
            if (!h) {
                const u64* pp = part + (buf * UGRP) * 128 + p;
#pragma unroll
                for (int j = 0; j < UGRP; ++j) {
                    u64 tot = add2(acc[j], pp[j * 128]);
                    // residual = x[sb+j] = win[31+j] for half 0
                    hbuf[(rl + j) * HBUF_PAIRS + slotc] =
                        fma2(tot, sc2, win[HTAPS - 1 + j]);
                }
            }

            // Slide window by UGRP.
#pragma unroll
            for (int i = 0; i < WSPAN - UGRP; ++i) win[i] = win[i + UGRP];
#pragma unroll
            for (int i = 0; i < UGRP; ++i) win[WSPAN - UGRP + i] = nxt[i];
        }
    }
    __syncthreads();   // hbuf complete -> LN epilogue

    // ---- LayerNorm epilogue: 8 warps, 8 rows each ----
    const int wid  = tid >> 5;
    const int lane = tid & 31;

    u64 g8[8], b8[8];
#pragma unroll
    for (int k = 0; k < 8; ++k) {
        g8[k] = reinterpret_cast<const u64*>(gamma)[lane + 32 * k];
        b8[k] = reinterpret_cast<const u64*>(beta)[lane + 32 * k];
    }

    float* __restrict__ ob = out + (size_t)b * (SEQ * HID) + (size_t)s0 * HID;

#pragma unroll 1
    for (int rr = 0; rr < SC / 8; ++rr) {
        const int r = wid + rr * 8;
        u64 v[8];
        float s = 0.f, qq = 0.f;
#pragma unroll
        for (int k = 0; k < 8; ++k) {
            v[k] = hbuf[r * HBUF_PAIRS + lane + 32 * k];
            float a = lo32(v[k]), bb = hi32(v[k]);
            s  += a + bb;
            qq += a * a + bb * bb;
        }
#pragma unroll
        for (int o = 16; o > 0; o >>= 1) {
            s  += __shfl_xor_sync(0xFFFFFFFFu, s, o);
            qq += __shfl_xor_sync(0xFFFFFFFFu, qq, o);
        }
        const float mean = s * (1.0f / HID);
        const float var  = qq * (1.0f / HID) - mean * mean;
        const float inv  = rsqrtf(var + 1e-12f);

        u64* __restrict__ orow = reinterpret_cast<u64*>(ob + r * HID);
#pragma unroll
        for (int k = 0; k < 8; ++k) {
            float a  = (lo32(v[k]) - mean) * inv;
            float bb = (hi32(v[k]) - mean) * inv;
            orow[lane + 32 * k] =
                pack2(lo32(g8[k]) * a + lo32(b8[k]),
                      hi32(g8[k]) * bb + hi32(b8[k]));
        }
    }
}

extern "C" void kernel_launch(void* const* d_in, const int* in_sizes, int n_in,
                              void* d_out, int out_size)
{
    const float* x     = (const float*)d_in[0];   // [B, 2048, 512] f32
    const float* w     = (const float*)d_in[1];   // [1, 64, 512]   f32
    const float* gamma = (const float*)d_in[2];   // [512]          f32
    const float* beta  = (const float*)d_in[3];   // [512]          f32
    float* out = (float*)d_out;

    const int B = in_sizes[0] / (SEQ * HID);
    const int smem = (SC * HBUF_PAIRS + 2 * UGRP * 128) * sizeof(u64);   // 144KB

    static bool attr_set = false;
    if (!attr_set) {
        cudaFuncSetAttribute(fconv_ln_kernel,
                             cudaFuncAttributeMaxDynamicSharedMemorySize, smem);
        attr_set = true;
    }

    dim3 grid(SEQ / SC, B);   // (32, B)
    fconv_ln_kernel<<<grid, 256, smem>>>(x, w, gamma, beta, out);
}

// round 13
// speedup vs baseline: 1.0613x; 1.0613x over previous
#include <cuda_runtime.h>
#include <cstdint>

#define SEQ   2048
#define HID   512
#define TAPS  64
#define SC    64       // seq rows per CTA
#define UGRP  8        // rows per inner group
#define HTAPS 32       // taps per pass
#define WSPAN (HTAPS + UGRP - 1)   // 39 live window rows
#define NPAIR 256      // u64 channel-pairs per row (= threads)

typedef unsigned long long u64;

__device__ __forceinline__ u64 fma2(u64 a, u64 b, u64 c) {
    u64 d;
    asm("fma.rn.f32x2 %0, %1, %2, %3;" : "=l"(d) : "l"(a), "l"(b), "l"(c));
    return d;
}
__device__ __forceinline__ float lo32(u64 v) { return __uint_as_float((unsigned)v); }
__device__ __forceinline__ float hi32(u64 v) { return __uint_as_float((unsigned)(v >> 32)); }
__device__ __forceinline__ u64 pack2(float l, float h) {
    return ((u64)__float_as_uint(h) << 32) | (u64)__float_as_uint(l);
}

// Fused circular depthwise conv (64 taps, f32x2) + residual + LayerNorm.
// 256 threads = 256 channel-pairs (all 512 channels). TAPS SPLIT IN TIME:
// pass 0 (taps 0..31, + scaled residual) writes h-partials to hbuf; pass 1
// (taps 32..63) read-modify-writes them. Each thread owns hbuf column p in
// both passes -> NO barrier / NO exchange in the conv (R1-style independent
// warps), register window + weights, f32x2 throughout. One __syncthreads
// before the LN epilogue.
extern __shared__ u64 hbuf[];   // [SC][NPAIR] = 128 KB

__global__ __launch_bounds__(256, 1) void fconv_ln_kernel(
    const float* __restrict__ x,
    const float* __restrict__ w,
    const float* __restrict__ gamma,
    const float* __restrict__ beta,
    float* __restrict__ out)
{
    const int tid = threadIdx.x;
    const int p   = tid;                 // channel pair 0..255
    const int b   = blockIdx.y;
    const int s0  = blockIdx.x * SC;

    const u64* __restrict__ xb =
        reinterpret_cast<const u64*>(x) + (size_t)b * SEQ * NPAIR + p;
    const u64* __restrict__ wp = reinterpret_cast<const u64*>(w) + p;

    const float ks = 0.022097086912079608f;   // 1/sqrt(2048)
    const u64 sc2 = pack2(ks, ks);

#pragma unroll 1
    for (int pass = 0; pass < 2; ++pass) {
        const int d  = pass ? 63 : 31;       // window start offset: s0 - d
        const int tb = pass ? HTAPS : 0;     // tap base

        // This pass's 32 tap-weights for this channel pair (registers).
        u64 wr[HTAPS];
#pragma unroll
        for (int t = 0; t < HTAPS; ++t)
            wr[t] = wp[(tb + t) * NPAIR];

        // Window: win[i] = x[(s0 - d + i) mod SEQ], i in [0,39)
        u64 win[WSPAN];
#pragma unroll
        for (int i = 0; i < WSPAN; ++i) {
            int row = (s0 - d + i + SEQ) & (SEQ - 1);
            win[i] = xb[(size_t)row * NPAIR];
        }

#pragma unroll 1
        for (int g = 0; g < SC / UGRP; ++g) {
            const int sb = s0 + g * UGRP;
            const int rl = g * UGRP;

            // Prefetch next UGRP window rows (hidden under this group's FMAs).
            u64 nxt[UGRP];
#pragma unroll
            for (int i = 0; i < UGRP; ++i) {
                int row = (sb - d + WSPAN + i + SEQ) & (SEQ - 1);
                nxt[i] = xb[(size_t)row * NPAIR];
            }

            // 32-tap partials: acc[j] = sum_t wr[t] * win[31+j-t]
            // (pass 0: rows sb+j-t; pass 1: rows sb+j-32-t)
            u64 acc[UGRP];
#pragma unroll
            for (int j = 0; j < UGRP; ++j) acc[j] = 0ull;
#pragma unroll 4
            for (int t = 0; t < HTAPS; ++t) {
#pragma unroll
                for (int j = 0; j < UGRP; ++j)
                    acc[j] = fma2(wr[t], win[HTAPS - 1 + j - t], acc[j]);
            }

            if (pass == 0) {
                // h_partial = acc*scale + x[sb+j]  (win[31+j] = row sb+j)
#pragma unroll
                for (int j = 0; j < UGRP; ++j)
                    hbuf[(rl + j) * NPAIR + p] =
                        fma2(acc[j], sc2, win[HTAPS - 1 + j]);
            } else {
                // h = h_partial + acc*scale   (same thread -> no sync needed)
#pragma unroll
                for (int j = 0; j < UGRP; ++j) {
                    u64 prev = hbuf[(rl + j) * NPAIR + p];
                    hbuf[(rl + j) * NPAIR + p] = fma2(acc[j], sc2, prev);
                }
            }

            // Slide window by UGRP.
#pragma unroll
            for (int i = 0; i < WSPAN - UGRP; ++i) win[i] = win[i + UGRP];
#pragma unroll
            for (int i = 0; i < UGRP; ++i) win[WSPAN - UGRP + i] = nxt[i];
        }
    }
    __syncthreads();   // hbuf complete -> LN epilogue

    // ---- LayerNorm epilogue: 8 warps, 8 rows each ----
    const int wid  = tid >> 5;
    const int lane = tid & 31;

    u64 g8[8], b8[8];
#pragma unroll
    for (int k = 0; k < 8; ++k) {
        g8[k] = reinterpret_cast<const u64*>(gamma)[lane + 32 * k];
        b8[k] = reinterpret_cast<const u64*>(beta)[lane + 32 * k];
    }

    float* __restrict__ ob = out + (size_t)b * (SEQ * HID) + (size_t)s0 * HID;

#pragma unroll 1
    for (int rr = 0; rr < SC / 8; ++rr) {
        const int r = wid + rr * 8;
        u64 v[8];
        float s = 0.f, qq = 0.f;
#pragma unroll
        for (int k = 0; k < 8; ++k) {
            v[k] = hbuf[r * NPAIR + lane + 32 * k];
            float a = lo32(v[k]), bb = hi32(v[k]);
            s  += a + bb;
            qq += a * a + bb * bb;
        }
#pragma unroll
        for (int o = 16; o > 0; o >>= 1) {
            s  += __shfl_xor_sync(0xFFFFFFFFu, s, o);
            qq += __shfl_xor_sync(0xFFFFFFFFu, qq, o);
        }
        const float mean = s * (1.0f / HID);
        const float var  = qq * (1.0f / HID) - mean * mean;
        const float inv  = rsqrtf(var + 1e-12f);

        u64* __restrict__ orow = reinterpret_cast<u64*>(ob + r * HID);
#pragma unroll
        for (int k = 0; k < 8; ++k) {
            float a  = (lo32(v[k]) - mean) * inv;
            float bb = (hi32(v[k]) - mean) * inv;
            orow[lane + 32 * k] =
                pack2(lo32(g8[k]) * a + lo32(b8[k]),
                      hi32(g8[k]) * bb + hi32(b8[k]));
        }
    }
}

extern "C" void kernel_launch(void* const* d_in, const int* in_sizes, int n_in,
                              void* d_out, int out_size)
{
    const float* x     = (const float*)d_in[0];   // [B, 2048, 512] f32
    const float* w     = (const float*)d_in[1];   // [1, 64, 512]   f32
    const float* gamma = (const float*)d_in[2];   // [512]          f32
    const float* beta  = (const float*)d_in[3];   // [512]          f32
    float* out = (float*)d_out;

    const int B = in_sizes[0] / (SEQ * HID);
    const int smem = SC * NPAIR * sizeof(u64);    // 128 KB

    static bool attr_set = false;
    if (!attr_set) {
        cudaFuncSetAttribute(fconv_ln_kernel,
                             cudaFuncAttributeMaxDynamicSharedMemorySize, smem);
        attr_set = true;
    }

    dim3 grid(SEQ / SC, B);   // (32, B)
    fconv_ln_kernel<<<grid, 256, smem>>>(x, w, gamma, beta, out);
}

// round 14
// speedup vs baseline: 2.8841x; 2.7176x over previous
#include <cuda_runtime.h>
#include <cstdint>

#define SEQ   2048
#define HID   512
#define TAPS  64
#define SC    64       // seq rows per CTA
#define UGRP  8        // rows per inner group
#define HTAPS 32       // taps per pass
#define WSPAN (HTAPS + UGRP - 1)   // 39 live window rows
#define NPAIR 256      // u64 channel-pairs per row (= threads)

typedef unsigned long long u64;

__device__ __forceinline__ u64 fma2(u64 a, u64 b, u64 c) {
    u64 d;
    asm("fma.rn.f32x2 %0, %1, %2, %3;" : "=l"(d) : "l"(a), "l"(b), "l"(c));
    return d;
}
__device__ __forceinline__ float lo32(u64 v) { return __uint_as_float((unsigned)v); }
__device__ __forceinline__ float hi32(u64 v) { return __uint_as_float((unsigned)(v >> 32)); }
__device__ __forceinline__ u64 pack2(float l, float h) {
    return ((u64)__float_as_uint(h) << 32) | (u64)__float_as_uint(l);
}

// Fused circular depthwise conv (64 taps, f32x2) + residual + LayerNorm.
// 256 threads = 256 channel-pairs (all 512 channels). Taps split IN TIME:
// pass 0 (taps 0..31, + scaled residual) writes h-partials to hbuf; pass 1
// (taps 32..63) read-modify-writes them. No barrier / no exchange in the conv.
// CRITICAL: tap loop is FULLY unrolled so all win[] indices are compile-time
// constants — partial unroll demotes the window to local memory (spills).
extern __shared__ u64 hbuf[];   // [SC][NPAIR] = 128 KB

__global__ __launch_bounds__(256, 1) void fconv_ln_kernel(
    const float* __restrict__ x,
    const float* __restrict__ w,
    const float* __restrict__ gamma,
    const float* __restrict__ beta,
    float* __restrict__ out)
{
    const int tid = threadIdx.x;
    const int p   = tid;                 // channel pair 0..255
    const int b   = blockIdx.y;
    const int s0  = blockIdx.x * SC;

    const u64* __restrict__ xb =
        reinterpret_cast<const u64*>(x) + (size_t)b * SEQ * NPAIR + p;
    const u64* __restrict__ wp = reinterpret_cast<const u64*>(w) + p;

    const float ks = 0.022097086912079608f;   // 1/sqrt(2048)
    const u64 sc2 = pack2(ks, ks);

#pragma unroll 1
    for (int pass = 0; pass < 2; ++pass) {
        const int d  = pass ? 63 : 31;       // window start offset: s0 - d
        const int tb = pass ? HTAPS : 0;     // tap base

        // This pass's 32 tap-weights for this channel pair (registers).
        u64 wr[HTAPS];
#pragma unroll
        for (int t = 0; t < HTAPS; ++t)
            wr[t] = wp[(tb + t) * NPAIR];

        // Window: win[i] = x[(s0 - d + i) mod SEQ], i in [0,39)
        u64 win[WSPAN];
#pragma unroll
        for (int i = 0; i < WSPAN; ++i) {
            int row = (s0 - d + i + SEQ) & (SEQ - 1);
            win[i] = xb[(size_t)row * NPAIR];
        }

#pragma unroll 1
        for (int g = 0; g < SC / UGRP; ++g) {
            const int sb = s0 + g * UGRP;
            const int rl = g * UGRP;

            // Prefetch next UGRP window rows (hidden under this group's FMAs).
            u64 nxt[UGRP];
#pragma unroll
            for (int i = 0; i < UGRP; ++i) {
                int row = (sb - d + WSPAN + i + SEQ) & (SEQ - 1);
                nxt[i] = xb[(size_t)row * NPAIR];
            }

            // 32-tap partials: acc[j] = sum_t wr[t] * win[31+j-t]
            // FULL unroll -> every win index is a compile-time constant.
            u64 acc[UGRP];
#pragma unroll
            for (int j = 0; j < UGRP; ++j) acc[j] = 0ull;
#pragma unroll
            for (int t = 0; t < HTAPS; ++t) {
#pragma unroll
                for (int j = 0; j < UGRP; ++j)
                    acc[j] = fma2(wr[t], win[HTAPS - 1 + j - t], acc[j]);
            }

            if (pass == 0) {
                // h_partial = acc*scale + x[sb+j]  (win[31+j] = row sb+j)
#pragma unroll
                for (int j = 0; j < UGRP; ++j)
                    hbuf[(rl + j) * NPAIR + p] =
                        fma2(acc[j], sc2, win[HTAPS - 1 + j]);
            } else {
                // h = h_partial + acc*scale   (same thread -> no sync needed)
#pragma unroll
                for (int j = 0; j < UGRP; ++j) {
                    u64 prev = hbuf[(rl + j) * NPAIR + p];
                    hbuf[(rl + j) * NPAIR + p] = fma2(acc[j], sc2, prev);
                }
            }

            // Slide window by UGRP.
#pragma unroll
            for (int i = 0; i < WSPAN - UGRP; ++i) win[i] = win[i + UGRP];
#pragma unroll
            for (int i = 0; i < UGRP; ++i) win[WSPAN - UGRP + i] = nxt[i];
        }
    }
    __syncthreads();   // hbuf complete -> LN epilogue

    // ---- LayerNorm epilogue: 8 warps, 8 rows each ----
    const int wid  = tid >> 5;
    const int lane = tid & 31;

    u64 g8[8], b8[8];
#pragma unroll
    for (int k = 0; k < 8; ++k) {
        g8[k] = reinterpret_cast<const u64*>(gamma)[lane + 32 * k];
        b8[k] = reinterpret_cast<const u64*>(beta)[lane + 32 * k];
    }

    float* __restrict__ ob = out + (size_t)b * (SEQ * HID) + (size_t)s0 * HID;

#pragma unroll 1
    for (int rr = 0; rr < SC / 8; ++rr) {
        const int r = wid + rr * 8;
        u64 v[8];
        float s = 0.f, qq = 0.f;
#pragma unroll
        for (int k = 0; k < 8; ++k) {
            v[k] = hbuf[r * NPAIR + lane + 32 * k];
            float a = lo32(v[k]), bb = hi32(v[k]);
            s  += a + bb;
            qq += a * a + bb * bb;
        }
#pragma unroll
        for (int o = 16; o > 0; o >>= 1) {
            s  += __shfl_xor_sync(0xFFFFFFFFu, s, o);
            qq += __shfl_xor_sync(0xFFFFFFFFu, qq, o);
        }
        const float mean = s * (1.0f / HID);
        const float var  = qq * (1.0f / HID) - mean * mean;
        const float inv  = rsqrtf(var + 1e-12f);

        u64* __restrict__ orow = reinterpret_cast<u64*>(ob + r * HID);
#pragma unroll
        for (int k = 0; k < 8; ++k) {
            float a  = (lo32(v[k]) - mean) * inv;
            float bb = (hi32(v[k]) - mean) * inv;
            orow[lane + 32 * k] =
                pack2(lo32(g8[k]) * a + lo32(b8[k]),
                      hi32(g8[k]) * bb + hi32(b8[k]));
        }
    }
}

extern "C" void kernel_launch(void* const* d_in, const int* in_sizes, int n_in,
                              void* d_out, int out_size)
{
    const float* x     = (const float*)d_in[0];   // [B, 2048, 512] f32
    const float* w     = (const float*)d_in[1];   // [1, 64, 512]   f32
    const float* gamma = (const float*)d_in[2];   // [512]          f32
    const float* beta  = (const float*)d_in[3];   // [512]          f32
    float* out = (float*)d_out;

    const int B = in_sizes[0] / (SEQ * HID);
    const int smem = SC * NPAIR * sizeof(u64);    // 128 KB

    static bool attr_set = false;
    if (!attr_set) {
        cudaFuncSetAttribute(fconv_ln_kernel,
                             cudaFuncAttributeMaxDynamicSharedMemorySize, smem);
        attr_set = true;
    }

    dim3 grid(SEQ / SC, B);   // (32, B)
    fconv_ln_kernel<<<grid, 256, smem>>>(x, w, gamma, beta, out);
}

// round 15
// speedup vs baseline: 3.0806x; 1.0681x over previous
#include <cuda_runtime.h>
#include <cstdint>

#define SEQ   2048
#define HID   512
#define TAPS  64
#define SC    64       // seq rows per CTA
#define HTAPS 32       // taps per pass
#define WSPAN 47       // live window rows (covers 2 groups of 8)
#define NPAIR 256      // u64 channel-pairs per row (= threads)
#define NPR   4        // group-pairs per pass (8 groups)

typedef unsigned long long u64;

__device__ __forceinline__ u64 fma2(u64 a, u64 b, u64 c) {
    u64 d;
    asm("fma.rn.f32x2 %0, %1, %2, %3;" : "=l"(d) : "l"(a), "l"(b), "l"(c));
    return d;
}
__device__ __forceinline__ float lo32(u64 v) { return __uint_as_float((unsigned)v); }
__device__ __forceinline__ float hi32(u64 v) { return __uint_as_float((unsigned)(v >> 32)); }
__device__ __forceinline__ u64 pack2(float l, float h) {
    return ((u64)__float_as_uint(h) << 32) | (u64)__float_as_uint(l);
}

// Fused circular depthwise conv (64 taps, f32x2) + residual + LayerNorm.
// 256 threads = 256 channel-pairs. Taps split IN TIME (pass0: taps 0..31 +
// residual -> hbuf; pass1: taps 32..63 RMW hbuf). No barrier in the conv.
// Group loop unrolled x2 over a 47-row register window: one 31-MOV slide per
// TWO groups; prefetch (16 rows/pair) uses a wrapped base + immediate offsets.
// All win[] indices compile-time (full unroll) — never let the window spill.
extern __shared__ u64 hbuf[];   // [SC][NPAIR] = 128 KB

__global__ __launch_bounds__(256, 1) void fconv_ln_kernel(
    const float* __restrict__ x,
    const float* __restrict__ w,
    const float* __restrict__ gamma,
    const float* __restrict__ beta,
    float* __restrict__ out)
{
    const int tid = threadIdx.x;
    const int p   = tid;
    const int b   = blockIdx.y;
    const int s0  = blockIdx.x * SC;

    const u64* __restrict__ xb =
        reinterpret_cast<const u64*>(x) + (size_t)b * SEQ * NPAIR + p;
    const u64* __restrict__ wp = reinterpret_cast<const u64*>(w) + p;

    const float ks = 0.022097086912079608f;   // 1/sqrt(2048)
    const u64 sc2 = pack2(ks, ks);

#pragma unroll 1
    for (int pass = 0; pass < 2; ++pass) {
        const int d  = pass ? 63 : 31;       // window base row: s0 - d
        const int tb = pass ? HTAPS : 0;     // tap base

        u64 wr[HTAPS];
#pragma unroll
        for (int t = 0; t < HTAPS; ++t)
            wr[t] = wp[(tb + t) * NPAIR];

        // Window: win[i] = x[(s0 - d + i) mod SEQ], i in [0,47)
        u64 win[WSPAN];
#pragma unroll
        for (int i = 0; i < WSPAN; ++i) {
            int row = (s0 - d + i + SEQ) & (SEQ - 1);
            win[i] = xb[(size_t)row * NPAIR];
        }

#pragma unroll 1
        for (int P = 0; P < NPR; ++P) {
            const int rl = 16 * P;           // local row base (group even)

            // Prefetch 16 consecutive rows rb+47..rb+62 (rb = s0-d+16P).
            u64 nxt[16];
            {
                const int row0 = s0 - d + 16 * P + 47;
                if ((unsigned)row0 <= (unsigned)(SEQ - 16)) {
                    const u64* bp = xb + (size_t)row0 * NPAIR;   // imm offsets
#pragma unroll
                    for (int i = 0; i < 16; ++i) nxt[i] = bp[(size_t)i * NPAIR];
                } else {
#pragma unroll
                    for (int i = 0; i < 16; ++i) {
                        int row = (row0 + i + 2 * SEQ) & (SEQ - 1);
                        nxt[i] = xb[(size_t)row * NPAIR];
                    }
                }
            }

            // ---- group even: rows sb..sb+7, acc[j] = sum_t wr[t]*win[31+j-t]
            {
                u64 acc[8];
#pragma unroll
                for (int j = 0; j < 8; ++j) acc[j] = 0ull;
#pragma unroll
                for (int t = 0; t < HTAPS; ++t) {
#pragma unroll
                    for (int j = 0; j < 8; ++j)
                        acc[j] = fma2(wr[t], win[31 + j - t], acc[j]);
                }
                if (pass == 0) {
#pragma unroll
                    for (int j = 0; j < 8; ++j)
                        hbuf[(rl + j) * NPAIR + p] =
                            fma2(acc[j], sc2, win[31 + j]);   // + residual
                } else {
#pragma unroll
                    for (int j = 0; j < 8; ++j) {
                        u64 prev = hbuf[(rl + j) * NPAIR + p];
                        hbuf[(rl + j) * NPAIR + p] = fma2(acc[j], sc2, prev);
                    }
                }
            }

            // ---- group odd: rows sb+8..sb+15, acc[j] = sum_t wr[t]*win[39+j-t]
            {
                u64 acc[8];
#pragma unroll
                for (int j = 0; j < 8; ++j) acc[j] = 0ull;
#pragma unroll
                for (int t = 0; t < HTAPS; ++t) {
#pragma unroll
                    for (int j = 0; j < 8; ++j)
                        acc[j] = fma2(wr[t], win[39 + j - t], acc[j]);
                }
                if (pass == 0) {
#pragma unroll
                    for (int j = 0; j < 8; ++j)
                        hbuf[(rl + 8 + j) * NPAIR + p] =
                            fma2(acc[j], sc2, win[39 + j]);   // + residual
                } else {
#pragma unroll
                    for (int j = 0; j < 8; ++j) {
                        u64 prev = hbuf[(rl + 8 + j) * NPAIR + p];
                        hbuf[(rl + 8 + j) * NPAIR + p] = fma2(acc[j], sc2, prev);
                    }
                }
            }

            // Slide window by 16 (once per pair).
#pragma unroll
            for (int i = 0; i < WSPAN - 16; ++i) win[i] = win[i + 16];
#pragma unroll
            for (int i = 0; i < 16; ++i) win[WSPAN - 16 + i] = nxt[i];
        }
    }
    __syncthreads();   // hbuf complete -> LN epilogue

    // ---- LayerNorm epilogue: 8 warps, 8 rows each ----
    const int wid  = tid >> 5;
    const int lane = tid & 31;

    u64 g8[8], b8[8];
#pragma unroll
    for (int k = 0; k < 8; ++k) {
        g8[k] = reinterpret_cast<const u64*>(gamma)[lane + 32 * k];
        b8[k] = reinterpret_cast<const u64*>(beta)[lane + 32 * k];
    }

    float* __restrict__ ob = out + (size_t)b * (SEQ * HID) + (size_t)s0 * HID;

#pragma unroll 1
    for (int rr = 0; rr < SC / 8; ++rr) {
        const int r = wid + rr * 8;
        u64 v[8];
        float s = 0.f, qq = 0.f;
#pragma unroll
        for (int k = 0; k < 8; ++k) {
            v[k] = hbuf[r * NPAIR + lane + 32 * k];
            float a = lo32(v[k]), bb = hi32(v[k]);
            s  += a + bb;
            qq += a * a + bb * bb;
        }
#pragma unroll
        for (int o = 16; o > 0; o >>= 1) {
            s  += __shfl_xor_sync(0xFFFFFFFFu, s, o);
            qq += __shfl_xor_sync(0xFFFFFFFFu, qq, o);
        }
        const float mean = s * (1.0f / HID);
        const float var  = qq * (1.0f / HID) - mean * mean;
        const float inv  = rsqrtf(var + 1e-12f);

        u64* __restrict__ orow = reinterpret_cast<u64*>(ob + r * HID);
#pragma unroll
        for (int k = 0; k < 8; ++k) {
            float a  = (lo32(v[k]) - mean) * inv;
            float bb = (hi32(v[k]) - mean) * inv;
            orow[lane + 32 * k] =
                pack2(lo32(g8[k]) * a + lo32(b8[k]),
                      hi32(g8[k]) * bb + hi32(b8[k]));
        }
    }
}

extern "C" void kernel_launch(void* const* d_in, const int* in_sizes, int n_in,
                              void* d_out, int out_size)
{
    const float* x     = (const float*)d_in[0];   // [B, 2048, 512] f32
    const float* w     = (const float*)d_in[1];   // [1, 64, 512]   f32
    const float* gamma = (const float*)d_in[2];   // [512]          f32
    const float* beta  = (const float*)d_in[3];   // [512]          f32
    float* out = (float*)d_out;

    const int B = in_sizes[0] / (SEQ * HID);
    const int smem = SC * NPAIR * sizeof(u64);    // 128 KB

    static bool attr_set = false;
    if (!attr_set) {
        cudaFuncSetAttribute(fconv_ln_kernel,
                             cudaFuncAttributeMaxDynamicSharedMemorySize, smem);
        attr_set = true;
    }

    dim3 grid(SEQ / SC, B);   // (32, B)
    fconv_ln_kernel<<<grid, 256, smem>>>(x, w, gamma, beta, out);
}

// round 16
// speedup vs baseline: 3.5207x; 1.1429x over previous
#include <cuda_runtime.h>
#include <cstdint>

#define SEQ   2048
#define HID   512
#define TAPS  64
#define SC    64       // seq rows per CTA
#define HTAPS 32       // taps per pass
#define NPAIR 256      // u64 channel-pairs per row (= threads)
#define WSLOT 64       // circular register-window slots (l mod 64)

typedef unsigned long long u64;

__device__ __forceinline__ u64 fma2(u64 a, u64 b, u64 c) {
    u64 d;
    asm("fma.rn.f32x2 %0, %1, %2, %3;" : "=l"(d) : "l"(a), "l"(b), "l"(c));
    return d;
}
__device__ __forceinline__ float lo32(u64 v) { return __uint_as_float((unsigned)v); }
__device__ __forceinline__ float hi32(u64 v) { return __uint_as_float((unsigned)(v >> 32)); }
__device__ __forceinline__ u64 pack2(float l, float h) {
    return ((u64)__float_as_uint(h) << 32) | (u64)__float_as_uint(l);
}

// Fused circular depthwise conv (64 taps, f32x2) + residual + LayerNorm.
// 256 threads = 256 channel-pairs. Taps split IN TIME (pass0: taps 0..31 +
// residual -> hbuf; pass1: taps 32..63 RMW hbuf); no barrier in the conv.
// The window is a 64-slot CIRCULAR register file: the 4 pair-iterations per
// pass are fully unrolled so every slot index is compile-time (phase 16/pair,
// 16*4 = 64 -> exact wrap). Prefetch LDGs land directly in dead slots — no
// window-slide MOVs, no nxt[] staging registers. Taps iterate DESCENDING so
// newly loaded rows are consumed last in the next pair (max LDG lead).
extern __shared__ u64 hbuf[];   // [SC][NPAIR] = 128 KB

__global__ __launch_bounds__(256, 1) void fconv_ln_kernel(
    const float* __restrict__ x,
    const float* __restrict__ w,
    const float* __restrict__ gamma,
    const float* __restrict__ beta,
    float* __restrict__ out)
{
    const int tid = threadIdx.x;
    const int p   = tid;
    const int b   = blockIdx.y;
    const int s0  = blockIdx.x * SC;

    const u64* __restrict__ xb =
        reinterpret_cast<const u64*>(x) + (size_t)b * SEQ * NPAIR + p;
    const u64* __restrict__ wp = reinterpret_cast<const u64*>(w) + p;

    const float ks = 0.022097086912079608f;   // 1/sqrt(2048)
    const u64 sc2 = pack2(ks, ks);

#pragma unroll 1
    for (int pass = 0; pass < 2; ++pass) {
        const int d  = pass ? 63 : 31;       // l = row - (s0 - d)
        const int tb = pass ? HTAPS : 0;     // tap base

        // This pass's 32 tap-weights (registers).
        u64 wr[HTAPS];
#pragma unroll
        for (int t = 0; t < HTAPS; ++t)
            wr[t] = wp[(tb + t) * NPAIR];

        // Circular window init: l = 0..46 -> slots 0..46.
        u64 win[WSLOT];
        {
            const int base = s0 - d;
            if (base >= 0) {   // fast path: contiguous, immediate offsets
                const u64* bp = xb + (size_t)base * NPAIR;
#pragma unroll
                for (int l = 0; l < 47; ++l) win[l] = bp[(size_t)l * NPAIR];
            } else {
#pragma unroll
                for (int l = 0; l < 47; ++l) {
                    int row = (base + l + SEQ) & (SEQ - 1);
                    win[l] = xb[(size_t)row * NPAIR];
                }
            }
        }

        // 4 pair-iterations, FULLY unrolled (static circular slot indices).
#pragma unroll
        for (int P = 0; P < 4; ++P) {
            // Prefetch pair P+1's 16 new rows: l = 16P+47 .. 16P+62 into
            // slots (l & 63) — dead since pair P-1. Consumed late in P+1.
            if (P < 3) {
                const int l0   = 16 * P + 47;
                const int row0 = s0 - d + l0;
                if (row0 >= 0 && row0 <= SEQ - 16) {
                    const u64* bp = xb + (size_t)row0 * NPAIR;
#pragma unroll
                    for (int i = 0; i < 16; ++i)
                        win[(l0 + i) & (WSLOT - 1)] = bp[(size_t)i * NPAIR];
                } else {
#pragma unroll
                    for (int i = 0; i < 16; ++i) {
                        int row = (row0 + i + 2 * SEQ) & (SEQ - 1);
                        win[(l0 + i) & (WSLOT - 1)] = xb[(size_t)row * NPAIR];
                    }
                }
            }

            const int rl = 16 * P;

            // ---- group even: rows r = 16P+j, l = 16P + j + 31 - u ----
            {
                u64 acc[8];
#pragma unroll
                for (int j = 0; j < 8; ++j) acc[j] = 0ull;
#pragma unroll
                for (int tt = 0; tt < HTAPS; ++tt) {
                    const int u = HTAPS - 1 - tt;   // descending taps
#pragma unroll
                    for (int j = 0; j < 8; ++j)
                        acc[j] = fma2(wr[u],
                                      win[(16 * P + j + 31 - u) & (WSLOT - 1)],
                                      acc[j]);
                }
                if (pass == 0) {
#pragma unroll
                    for (int j = 0; j < 8; ++j)
                        hbuf[(rl + j) * NPAIR + p] =
                            fma2(acc[j], sc2,
                                 win[(16 * P + j + 31) & (WSLOT - 1)]);
                } else {
#pragma unroll
                    for (int j = 0; j < 8; ++j) {
                        u64 prev = hbuf[(rl + j) * NPAIR + p];
                        hbuf[(rl + j) * NPAIR + p] = fma2(acc[j], sc2, prev);
                    }
                }
            }

            // ---- group odd: rows r = 16P+8+j, l = 16P + 8 + j + 31 - u ----
            {
                u64 acc[8];
#pragma unroll
                for (int j = 0; j < 8; ++j) acc[j] = 0ull;
#pragma unroll
                for (int tt = 0; tt < HTAPS; ++tt) {
                    const int u = HTAPS - 1 - tt;
#pragma unroll
                    for (int j = 0; j < 8; ++j)
                        acc[j] = fma2(wr[u],
                                      win[(16 * P + 39 + j - u) & (WSLOT - 1)],
                                      acc[j]);
                }
                if (pass == 0) {
#pragma unroll
                    for (int j = 0; j < 8; ++j)
                        hbuf[(rl + 8 + j) * NPAIR + p] =
                            fma2(acc[j], sc2,
                                 win[(16 * P + 39 + j) & (WSLOT - 1)]);
                } else {
#pragma unroll
                    for (int j = 0; j < 8; ++j) {
                        u64 prev = hbuf[(rl + 8 + j) * NPAIR + p];
                        hbuf[(rl + 8 + j) * NPAIR + p] = fma2(acc[j], sc2, prev);
                    }
                }
            }
        }
    }
    __syncthreads();   // hbuf complete -> LN epilogue

    // ---- LayerNorm epilogue: 8 warps, 8 rows each ----
    const int wid  = tid >> 5;
    const int lane = tid & 31;

    u64 g8[8], b8[8];
#pragma unroll
    for (int k = 0; k < 8; ++k) {
        g8[k] = reinterpret_cast<const u64*>(gamma)[lane + 32 * k];
        b8[k] = reinterpret_cast<const u64*>(beta)[lane + 32 * k];
    }

    float* __restrict__ ob = out + (size_t)b * (SEQ * HID) + (size_t)s0 * HID;

#pragma unroll 1
    for (int rr = 0; rr < SC / 8; ++rr) {
        const int r = wid + rr * 8;
        u64 v[8];
        float s = 0.f, qq = 0.f;
#pragma unroll
        for (int k = 0; k < 8; ++k) {
            v[k] = hbuf[r * NPAIR + lane + 32 * k];
            float a = lo32(v[k]), bb = hi32(v[k]);
            s  += a + bb;
            qq += a * a + bb * bb;
        }
#pragma unroll
        for (int o = 16; o > 0; o >>= 1) {
            s  += __shfl_xor_sync(0xFFFFFFFFu, s, o);
            qq += __shfl_xor_sync(0xFFFFFFFFu, qq, o);
        }
        const float mean = s * (1.0f / HID);
        const float var  = qq * (1.0f / HID) - mean * mean;
        const float inv  = rsqrtf(var + 1e-12f);

        u64* __restrict__ orow = reinterpret_cast<u64*>(ob + r * HID);
#pragma unroll
        for (int k = 0; k < 8; ++k) {
            float a  = (lo32(v[k]) - mean) * inv;
            float bb = (hi32(v[k]) - mean) * inv;
            orow[lane + 32 * k] =
                pack2(lo32(g8[k]) * a + lo32(b8[k]),
                      hi32(g8[k]) * bb + hi32(b8[k]));
        }
    }
}

extern "C" void kernel_launch(void* const* d_in, const int* in_sizes, int n_in,
                              void* d_out, int out_size)
{
    const float* x     = (const float*)d_in[0];   // [B, 2048, 512] f32
    const float* w     = (const float*)d_in[1];   // [1, 64, 512]   f32
    const float* gamma = (const float*)d_in[2];   // [512]          f32
    const float* beta  = (const float*)d_in[3];   // [512]          f32
    float* out = (float*)d_out;

    const int B = in_sizes[0] / (SEQ * HID);
    const int smem = SC * NPAIR * sizeof(u64);    // 128 KB

    static bool attr_set = false;
    if (!attr_set) {
        cudaFuncSetAttribute(fconv_ln_kernel,
                             cudaFuncAttributeMaxDynamicSharedMemorySize, smem);
        attr_set = true;
    }

    dim3 grid(SEQ / SC, B);   // (32, B)
    fconv_ln_kernel<<<grid, 256, smem>>>(x, w, gamma, beta, out);
}